// round 13
// baseline (speedup 1.0000x reference)
#include <cuda_runtime.h>
#include <cuda_fp16.h>
#include <cstdint>

#define BATCH   4
#define HEADS   16
#define SEQ     2048
#define DMODEL  1024
#define HDIM    64
#define TOK     (BATCH*SEQ)       // 8192
// softmax in exp2 domain: scale = (1/sqrt(64)) * log2(e)
#define SCALE2  0.18033688011112042f

#define QB      128               // query rows per fused block
#define TC      64                // key tile (pass 2)
#define TC1     128               // key tile (pass 1, stats only)

// -------- scratch (allocation-free rule: __device__ globals) --------
__device__ __half g_Q[BATCH*HEADS*SEQ*HDIM];   // [b][h][l][dh]
__device__ __half g_K[BATCH*HEADS*SEQ*HDIM];   // [b][h][t][dh]
__device__ __half g_V[BATCH*HEADS*SEQ*HDIM];   // [b][h][dh][t]  (transposed!)
__device__ __half g_O[TOK*DMODEL];             // [b*l][h*64+dv]
__device__ __half g_Xh[3*TOK*DMODEL];          // fp16 copies of q,k,v inputs
__device__ __half g_Wh[4*DMODEL*DMODEL];       // fp16 copies of Wq,Wk,Wv,Wo

__device__ __forceinline__ float ex2(float x) {
    float r;
    asm("ex2.approx.f32 %0, %1;" : "=f"(r) : "f"(x));
    return r;
}
__device__ __forceinline__ float lg2(float x) {
    float r;
    asm("lg2.approx.f32 %0, %1;" : "=f"(r) : "f"(x));
    return r;
}

__device__ __forceinline__ uint32_t f2h2(float lo, float hi) {
    __half2 h = __floats2half2_rn(lo, hi);
    return *reinterpret_cast<uint32_t*>(&h);
}

__device__ __forceinline__ void mma_f16(float c[4],
    uint32_t a0, uint32_t a1, uint32_t a2, uint32_t a3,
    uint32_t b0, uint32_t b1)
{
    asm volatile(
        "mma.sync.aligned.m16n8k16.row.col.f32.f16.f16.f32 "
        "{%0,%1,%2,%3}, {%4,%5,%6,%7}, {%8,%9}, {%0,%1,%2,%3};\n"
        : "+f"(c[0]), "+f"(c[1]), "+f"(c[2]), "+f"(c[3])
        : "r"(a0), "r"(a1), "r"(a2), "r"(a3), "r"(b0), "r"(b1));
}

__device__ __forceinline__ void ldsm_x4(uint32_t r[4], uint32_t addr) {
    asm volatile("ldmatrix.sync.aligned.m8n8.x4.shared.b16 {%0,%1,%2,%3}, [%4];"
        : "=r"(r[0]), "=r"(r[1]), "=r"(r[2]), "=r"(r[3]) : "r"(addr));
}
__device__ __forceinline__ void ldsm_x4_t(uint32_t r[4], uint32_t addr) {
    asm volatile("ldmatrix.sync.aligned.m8n8.x4.trans.shared.b16 {%0,%1,%2,%3}, [%4];"
        : "=r"(r[0]), "=r"(r[1]), "=r"(r[2]), "=r"(r[3]) : "r"(addr));
}

__device__ __forceinline__ uint32_t smem_u32(const void* p) {
    uint32_t a;
    asm("{ .reg .u64 t; cvta.to.shared.u64 t, %1; cvt.u32.u64 %0, t; }"
        : "=r"(a) : "l"(p));
    return a;
}
__device__ __forceinline__ void cp16(uint32_t dst, const void* src) {
    asm volatile("cp.async.cg.shared.global [%0], [%1], 16;" :: "r"(dst), "l"(src));
}
__device__ __forceinline__ void cp_commit() {
    asm volatile("cp.async.commit_group;" ::: "memory");
}
__device__ __forceinline__ void cp_wait1() {
    asm volatile("cp.async.wait_group 1;" ::: "memory");
}
__device__ __forceinline__ void cp_wait0() {
    asm volatile("cp.async.wait_group 0;" ::: "memory");
}

#define NEG_INF __int_as_float(0xff800000)

// ============================================================================
// fp32 -> fp16 converters, merged launches.
// ============================================================================
__device__ __forceinline__ void cvt_chunk(const float* __restrict__ src,
                                          __half* __restrict__ dst, int j)
{
    float4 a = ((const float4*)src)[j * 2];
    float4 b = ((const float4*)src)[j * 2 + 1];
    uint4 o;
    o.x = f2h2(a.x, a.y); o.y = f2h2(a.z, a.w);
    o.z = f2h2(b.x, b.y); o.w = f2h2(b.z, b.w);
    ((uint4*)dst)[j] = o;
}

__global__ void __launch_bounds__(256)
cvt3(const float* __restrict__ s0, const float* __restrict__ s1,
     const float* __restrict__ s2, __half* __restrict__ dst, int n8)
{
    int i = blockIdx.x * 256 + threadIdx.x;
    int which = i / n8, j = i - which * n8;
    const float* src = (which == 0) ? s0 : (which == 1) ? s1 : s2;
    cvt_chunk(src, dst + (size_t)which * n8 * 8, j);
}

__global__ void __launch_bounds__(256)
cvt4(const float* __restrict__ s0, const float* __restrict__ s1,
     const float* __restrict__ s2, const float* __restrict__ s3,
     __half* __restrict__ dst, int n8)
{
    int i = blockIdx.x * 256 + threadIdx.x;
    int which = i / n8, j = i - which * n8;
    const float* src = (which == 0) ? s0 : (which == 1) ? s1 :
                       (which == 2) ? s2 : s3;
    cvt_chunk(src, dst + (size_t)which * n8 * 8, j);
}

// ============================================================================
// fp16 projection GEMM: cp.async 3-stage, BK=64, ONE sync/iter.
// C[8192x1024] = A(fp16) @ W(fp16) + bias(fp32).
//  EPI 0: fp32 row-major out.
//  EPI 1: fp16 scatter. z<2 -> [b][h][l][dh]; z==2 -> V transposed [b][h][dh][t].
// smem halves: As[3] 128x72 @ buf*9216 | Bs[3] 64x136 @ 27648+buf*8704
// total 53760 halves = 107520 B.
// ============================================================================
#define PAS 72
#define PBS 136
#define PJ_AS_H(buf) ((buf) * 9216)
#define PJ_BS_H(buf) (27648 + (buf) * 8704)
#define PJ_SMEM_BYTES 107520

template<int EPI>
__global__ void __launch_bounds__(256, 2)
proj_gemm(const __half* __restrict__ A0, const __half* __restrict__ A1,
          const __half* __restrict__ A2,
          const __half* __restrict__ W0, const __half* __restrict__ W1,
          const __half* __restrict__ W2,
          const float* __restrict__ b0, const float* __restrict__ b1,
          const float* __restrict__ b2,
          void* o0v, void* o1v, void* o2v)
{
    extern __shared__ char smc[];
    const uint32_t sb = smem_u32(smc);

    const int z = blockIdx.z;
    const __half* Ag  = (z == 0) ? A0 : (z == 1) ? A1 : A2;
    const __half* Wg  = (z == 0) ? W0 : (z == 1) ? W1 : W2;
    const float* bias = (z == 0) ? b0 : (z == 1) ? b1 : b2;
    void* outv        = (z == 0) ? o0v : (z == 1) ? o1v : o2v;

    const int tid  = threadIdx.x;
    const int warp = tid >> 5;
    const int lane = tid & 31;
    const int wm   = warp & 3;
    const int wn   = warp >> 2;
    const int g    = lane >> 2;
    const int t4   = lane & 3;
    const int l15  = lane & 15;
    const int lhi  = (lane >> 4) * 8;

    const int bn = blockIdx.x * 128;
    const int bm = blockIdx.y * 128;

    float acc[2][8][4];
    #pragma unroll
    for (int mi = 0; mi < 2; ++mi)
        #pragma unroll
        for (int ni = 0; ni < 8; ++ni)
            #pragma unroll
            for (int e = 0; e < 4; ++e) acc[mi][ni][e] = 0.f;

    auto issue = [&](int t, int buf) {
        const int kg = t * 64;
        const uint32_t ab = sb + PJ_AS_H(buf) * 2;
        #pragma unroll
        for (int i = 0; i < 4; ++i) {
            int idx = i * 256 + tid;
            int r = idx >> 3, c = idx & 7;
            cp16(ab + (r * PAS + c * 8) * 2, Ag + (size_t)(bm + r) * DMODEL + kg + c * 8);
        }
        const uint32_t bb = sb + PJ_BS_H(buf) * 2;
        #pragma unroll
        for (int i = 0; i < 4; ++i) {
            int idx = i * 256 + tid;
            int r = idx >> 4, c = idx & 15;
            cp16(bb + (r * PBS + c * 8) * 2, Wg + (size_t)(kg + r) * DMODEL + bn + c * 8);
        }
    };

    auto compute = [&](int buf, int kk) {
        const uint32_t asb = sb + PJ_AS_H(buf) * 2;
        const uint32_t bsb = sb + PJ_BS_H(buf) * 2;
        uint32_t af[2][4];
        #pragma unroll
        for (int mi = 0; mi < 2; ++mi)
            ldsm_x4(af[mi], asb + ((wm * 32 + mi * 16 + l15) * PAS + kk + lhi) * 2);
        uint32_t bf[4][4];
        #pragma unroll
        for (int p = 0; p < 4; ++p)
            ldsm_x4_t(bf[p], bsb + ((kk + l15) * PBS + wn * 64 + p * 16 + lhi) * 2);
        #pragma unroll
        for (int mi = 0; mi < 2; ++mi)
            #pragma unroll
            for (int p = 0; p < 4; ++p) {
                mma_f16(acc[mi][2 * p    ], af[mi][0], af[mi][1], af[mi][2], af[mi][3],
                        bf[p][0], bf[p][1]);
                mma_f16(acc[mi][2 * p + 1], af[mi][0], af[mi][1], af[mi][2], af[mi][3],
                        bf[p][2], bf[p][3]);
            }
    };

    issue(0, 0); cp_commit();
    issue(1, 1); cp_commit();
    for (int t = 0; t < 16; ++t) {
        cp_wait1();                            // tile t arrived
        __syncthreads();                       // visibility + buffer protection
        if (t + 2 < 16) issue(t + 2, (t + 2) % 3);
        cp_commit();                           // unconditional: 1 group/iter
        const int buf = t % 3;
        compute(buf, 0);
        compute(buf, 16);
        compute(buf, 32);
        compute(buf, 48);
    }

    // ---- epilogue ----
    #pragma unroll
    for (int mi = 0; mi < 2; ++mi) {
        #pragma unroll
        for (int ni = 0; ni < 8; ++ni) {
            int row0 = bm + wm * 32 + mi * 16 + g;
            int col  = bn + wn * 64 + ni * 8 + t4 * 2;
            float v00 = acc[mi][ni][0] + bias[col];
            float v01 = acc[mi][ni][1] + bias[col + 1];
            float v10 = acc[mi][ni][2] + bias[col];
            float v11 = acc[mi][ni][3] + bias[col + 1];
            if (EPI == 0) {
                float* out = (float*)outv;
                *(float2*)(out + (size_t)row0 * DMODEL + col) = make_float2(v00, v01);
                *(float2*)(out + (size_t)(row0 + 8) * DMODEL + col) = make_float2(v10, v11);
            } else {
                __half* out = (__half*)outv;
                int h  = col >> 6;
                int dh = col & 63;
                if (z < 2) {
                    #pragma unroll
                    for (int rr = 0; rr < 2; ++rr) {
                        int row = row0 + rr * 8;
                        int b = row >> 11, l = row & (SEQ - 1);
                        uint32_t pv = rr ? f2h2(v10, v11) : f2h2(v00, v01);
                        *(uint32_t*)(out + (((size_t)(b * HEADS + h)) * SEQ + l) * HDIM + dh) = pv;
                    }
                } else {
                    // V transposed: [b][h][dh][t]
                    #pragma unroll
                    for (int rr = 0; rr < 2; ++rr) {
                        int row = row0 + rr * 8;
                        int b = row >> 11, l = row & (SEQ - 1);
                        float va = rr ? v10 : v00;
                        float vb = rr ? v11 : v01;
                        size_t base = ((size_t)(b * HEADS + h)) * HDIM;
                        out[(base + dh    ) * SEQ + l] = __float2half_rn(va);
                        out[(base + dh + 1) * SEQ + l] = __float2half_rn(vb);
                    }
                }
            }
        }
    }
}

// ============================================================================
// Fused attention fp16. Pass 1: TC1=128 key tiles (stats only, sacc[16][4]);
// pass 2: TC=64 tiles, recompute + fold-normalized attn write + PV.
// smem region bytes [0, 55296): pass1 KS[3] @ buf*18432 (128x72 halves);
//                               pass2 KS[3] @ buf*9216, VS[3] @ 27648+buf*9216.
// Mf fp32 @ byte 55296 (2048 floats). Qs[128][72] overlays buf0 during init.
// ============================================================================
#define FST 72
#define KS1_B(buf) ((buf) * 18432)            // pass-1 K buffers (bytes)
#define KS2_B(buf) ((buf) * 9216)             // pass-2 K buffers (bytes)
#define VS2_B(buf) (27648 + (buf) * 9216)     // pass-2 V buffers (bytes)
#define FA_SMEM_BYTES 63488

__global__ void __launch_bounds__(256, 2)
fused_attn(const __half* __restrict__ gQ, const __half* __restrict__ gK,
           const __half* __restrict__ gVt, const int* __restrict__ mask,
           float* __restrict__ attnOut, __half* __restrict__ gO)
{
    extern __shared__ char smc[];
    __half* smh = (__half*)smc;
    float*  Mf  = (float*)(smc + 55296);
    const uint32_t sb = smem_u32(smc);

    const int tid  = threadIdx.x;
    const int lane = tid & 31;
    const int warp = tid >> 5;
    const int g    = lane >> 2;
    const int t4   = lane & 3;
    const int l15  = lane & 15;
    const int lhi  = (lane >> 4) * 8;
    const int wrow = warp * 16;

    const int qb = blockIdx.x * QB;
    const int bh = blockIdx.y;
    const int zb = bh >> 4;
    const int zh = bh & 15;

    const __half* Q  = gQ + ((size_t)bh * SEQ + qb) * HDIM;
    const __half* K  = gK + (size_t)bh * SEQ * HDIM;
    const __half* Vt = gVt + (size_t)bh * HDIM * SEQ;
    float* attn = attnOut + ((size_t)(zh * BATCH + zb) * SEQ + qb) * SEQ;

    // mask -> additive float
    #pragma unroll
    for (int i = 0; i < SEQ / 256; ++i) {
        int c = i * 256 + tid;
        Mf[c] = mask[zb * SEQ + c] ? NEG_INF : 0.f;
    }
    // Q tile -> smem (overlay on pass-1 buf0)
    #pragma unroll
    for (int i = 0; i < 4; ++i) {
        int idx = i * 256 + tid;
        int r = idx >> 3, c = idx & 7;
        *(uint4*)(smh + r * FST + c * 8) = *(const uint4*)(Q + (size_t)r * HDIM + c * 8);
    }
    __syncthreads();

    // persistent Q A-fragments: 4 k16-steps x 4 regs
    uint32_t aq[4][4];
    #pragma unroll
    for (int ks = 0; ks < 4; ++ks)
        ldsm_x4(aq[ks], sb + ((wrow + l15) * FST + ks * 16 + lhi) * 2);
    __syncthreads();   // Qs dead before cp.async reuses region

    // ---- pass-1 stager: K tile 128 rows ----
    auto issueK1 = [&](int t, int buf) {
        const __half* Kt = K + (size_t)t * TC1 * HDIM;
        const uint32_t base = sb + KS1_B(buf);
        #pragma unroll
        for (int i = 0; i < 4; ++i) {
            int idx = i * 256 + tid;
            int r = idx >> 3, c = idx & 7;
            cp16(base + (r * FST + c * 8) * 2, Kt + r * HDIM + c * 8);
        }
    };
    // ---- pass-2 stagers: K/V tiles 64 rows ----
    auto issueK2 = [&](int t, int buf) {
        const __half* Kt = K + (size_t)t * TC * HDIM;
        const uint32_t base = sb + KS2_B(buf);
        #pragma unroll
        for (int i = 0; i < 2; ++i) {
            int idx = i * 256 + tid;
            int r = idx >> 3, c = idx & 7;
            cp16(base + (r * FST + c * 8) * 2, Kt + r * HDIM + c * 8);
        }
    };
    auto issueV2 = [&](int t, int buf) {
        const __half* Vs = Vt + (size_t)t * TC;   // [dv][t] tile
        const uint32_t base = sb + VS2_B(buf);
        #pragma unroll
        for (int i = 0; i < 2; ++i) {
            int idx = i * 256 + tid;
            int r = idx >> 3, c = idx & 7;
            cp16(base + (r * FST + c * 8) * 2, Vs + (size_t)r * SEQ + c * 8);
        }
    };

    // ---------------- pass 1: online (m, l), TC1=128 ----------------
    float m0 = NEG_INF, m1 = NEG_INF, l0 = 0.f, l1 = 0.f;

    issueK1(0, 0); cp_commit();
    issueK1(1, 1); cp_commit();
    for (int t = 0; t < SEQ / TC1; ++t) {
        cp_wait1();
        __syncthreads();
        if (t + 2 < SEQ / TC1) issueK1(t + 2, (t + 2) % 3);
        cp_commit();

        const uint32_t ksb = sb + KS1_B(t % 3);
        float sacc[16][4];
        #pragma unroll
        for (int nt = 0; nt < 16; ++nt)
            #pragma unroll
            for (int e = 0; e < 4; ++e) sacc[nt][e] = 0.f;
        #pragma unroll
        for (int ks = 0; ks < 4; ++ks) {
            uint32_t bf[8][4];
            #pragma unroll
            for (int p = 0; p < 8; ++p)
                ldsm_x4(bf[p], ksb + ((p * 16 + l15) * FST + ks * 16 + lhi) * 2);
            #pragma unroll
            for (int p = 0; p < 8; ++p) {
                mma_f16(sacc[2 * p    ], aq[ks][0], aq[ks][1], aq[ks][2], aq[ks][3],
                        bf[p][0], bf[p][2]);
                mma_f16(sacc[2 * p + 1], aq[ks][0], aq[ks][1], aq[ks][2], aq[ks][3],
                        bf[p][1], bf[p][3]);
            }
        }

        float tm0 = NEG_INF, tm1 = NEG_INF;
        #pragma unroll
        for (int nt = 0; nt < 16; ++nt) {
            float2 mk = *(const float2*)(Mf + t * TC1 + nt * 8 + t4 * 2);
            sacc[nt][0] = sacc[nt][0] * SCALE2 + mk.x;
            sacc[nt][1] = sacc[nt][1] * SCALE2 + mk.y;
            sacc[nt][2] = sacc[nt][2] * SCALE2 + mk.x;
            sacc[nt][3] = sacc[nt][3] * SCALE2 + mk.y;
            tm0 = fmaxf(tm0, fmaxf(sacc[nt][0], sacc[nt][1]));
            tm1 = fmaxf(tm1, fmaxf(sacc[nt][2], sacc[nt][3]));
        }
        tm0 = fmaxf(tm0, __shfl_xor_sync(0xffffffffu, tm0, 1));
        tm0 = fmaxf(tm0, __shfl_xor_sync(0xffffffffu, tm0, 2));
        tm1 = fmaxf(tm1, __shfl_xor_sync(0xffffffffu, tm1, 1));
        tm1 = fmaxf(tm1, __shfl_xor_sync(0xffffffffu, tm1, 2));

        float mn0 = fmaxf(m0, tm0), mn1 = fmaxf(m1, tm1);
        float ms0 = (mn0 == NEG_INF) ? 0.f : mn0;
        float ms1 = (mn1 == NEG_INF) ? 0.f : mn1;

        float sum0 = 0.f, sum1 = 0.f;
        #pragma unroll
        for (int nt = 0; nt < 16; ++nt) {
            sum0 += ex2(sacc[nt][0] - ms0) + ex2(sacc[nt][1] - ms0);
            sum1 += ex2(sacc[nt][2] - ms1) + ex2(sacc[nt][3] - ms1);
        }
        sum0 += __shfl_xor_sync(0xffffffffu, sum0, 1);
        sum0 += __shfl_xor_sync(0xffffffffu, sum0, 2);
        sum1 += __shfl_xor_sync(0xffffffffu, sum1, 1);
        sum1 += __shfl_xor_sync(0xffffffffu, sum1, 2);

        float a0 = (m0 == NEG_INF) ? 0.f : ex2(m0 - ms0);
        float a1 = (m1 == NEG_INF) ? 0.f : ex2(m1 - ms1);
        l0 = l0 * a0 + sum0;
        l1 = l1 * a1 + sum1;
        m0 = mn0; m1 = mn1;
    }

    // fold 1/l into exponent: c = m + log2(l)
    const float c0 = (l0 > 0.f) ? ((m0 == NEG_INF) ? 0.f : m0) + lg2(l0) : 0.f;
    const float c1 = (l1 > 0.f) ? ((m1 == NEG_INF) ? 0.f : m1) + lg2(l1) : 0.f;

    // ---------------- pass 2: recompute + P write + PV, TC=64 ----------------
    float oacc[8][4];
    #pragma unroll
    for (int nt = 0; nt < 8; ++nt)
        #pragma unroll
        for (int e = 0; e < 4; ++e) oacc[nt][e] = 0.f;

    cp_wait0();        // drain pass-1 prefetch groups before region re-layout
    __syncthreads();   // all warps past pass-1 compute
    issueK2(0, 0); issueV2(0, 0); cp_commit();
    issueK2(1, 1); issueV2(1, 1); cp_commit();
    for (int t = 0; t < SEQ / TC; ++t) {
        cp_wait1();
        __syncthreads();
        if (t + 2 < SEQ / TC) { issueK2(t + 2, (t + 2) % 3); issueV2(t + 2, (t + 2) % 3); }
        cp_commit();

        const uint32_t ksb = sb + KS2_B(t % 3);
        const uint32_t vsb = sb + VS2_B(t % 3);

        float sacc[8][4];
        #pragma unroll
        for (int nt = 0; nt < 8; ++nt)
            #pragma unroll
            for (int e = 0; e < 4; ++e) sacc[nt][e] = 0.f;
        #pragma unroll
        for (int ks = 0; ks < 4; ++ks) {
            uint32_t bf[4][4];
            #pragma unroll
            for (int p = 0; p < 4; ++p)
                ldsm_x4(bf[p], ksb + ((p * 16 + l15) * FST + ks * 16 + lhi) * 2);
            #pragma unroll
            for (int p = 0; p < 4; ++p) {
                mma_f16(sacc[2 * p    ], aq[ks][0], aq[ks][1], aq[ks][2], aq[ks][3],
                        bf[p][0], bf[p][2]);
                mma_f16(sacc[2 * p + 1], aq[ks][0], aq[ks][1], aq[ks][2], aq[ks][3],
                        bf[p][1], bf[p][3]);
            }
        }

        // normalize in place + streaming attn write (float2, sector-aligned)
        #pragma unroll
        for (int nt = 0; nt < 8; ++nt) {
            float2 mk = *(const float2*)(Mf + t * TC + nt * 8 + t4 * 2);
            sacc[nt][0] = ex2(sacc[nt][0] * SCALE2 + (mk.x - c0));
            sacc[nt][1] = ex2(sacc[nt][1] * SCALE2 + (mk.y - c0));
            sacc[nt][2] = ex2(sacc[nt][2] * SCALE2 + (mk.x - c1));
            sacc[nt][3] = ex2(sacc[nt][3] * SCALE2 + (mk.y - c1));
            float2* d0 = (float2*)(attn + (size_t)(wrow + g) * SEQ + t * TC + nt * 8 + t4 * 2);
            __stcs(d0, make_float2(sacc[nt][0], sacc[nt][1]));
            __stcs((float2*)((float*)d0 + 8 * SEQ), make_float2(sacc[nt][2], sacc[nt][3]));
        }

        // PV: A-frags straight from sacc (fp16 C-layout == A-layout)
        #pragma unroll
        for (int j = 0; j < 4; ++j) {
            uint32_t pa0 = f2h2(sacc[2 * j][0],     sacc[2 * j][1]);
            uint32_t pa1 = f2h2(sacc[2 * j][2],     sacc[2 * j][3]);
            uint32_t pa2 = f2h2(sacc[2 * j + 1][0], sacc[2 * j + 1][1]);
            uint32_t pa3 = f2h2(sacc[2 * j + 1][2], sacc[2 * j + 1][3]);
            uint32_t bf[4][4];
            #pragma unroll
            for (int p = 0; p < 4; ++p)
                ldsm_x4(bf[p], vsb + ((p * 16 + l15) * FST + j * 16 + lhi) * 2);
            #pragma unroll
            for (int p = 0; p < 4; ++p) {
                mma_f16(oacc[2 * p    ], pa0, pa1, pa2, pa3, bf[p][0], bf[p][2]);
                mma_f16(oacc[2 * p + 1], pa0, pa1, pa2, pa3, bf[p][1], bf[p][3]);
            }
        }
    }

    // write O block (fp16) to g_O [b*l][h*64+dv]
    #pragma unroll
    for (int nt = 0; nt < 8; ++nt) {
        int col = nt * 8 + t4 * 2;
        size_t r0 = ((size_t)zb * SEQ + qb + wrow + g) * DMODEL + zh * HDIM + col;
        *(uint32_t*)(gO + r0)               = f2h2(oacc[nt][0], oacc[nt][1]);
        *(uint32_t*)(gO + r0 + 8 * DMODEL)  = f2h2(oacc[nt][2], oacc[nt][3]);
    }
}

// ============================================================================
extern "C" void kernel_launch(void* const* d_in, const int* in_sizes, int n_in,
                              void* d_out, int out_size)
{
    const float* q    = (const float*)d_in[0];
    const float* k    = (const float*)d_in[1];
    const float* v    = (const float*)d_in[2];
    const int*   mask = (const int*)d_in[3];
    const float* Wq = (const float*)d_in[4];
    const float* bq = (const float*)d_in[5];
    const float* Wk = (const float*)d_in[6];
    const float* bk = (const float*)d_in[7];
    const float* Wv = (const float*)d_in[8];
    const float* bv = (const float*)d_in[9];
    const float* Wo = (const float*)d_in[10];
    const float* bo = (const float*)d_in[11];

    float* out  = (float*)d_out;                         // [4,2048,1024]
    float* attn = out + (size_t)TOK * DMODEL;            // [16,4,2048,2048]

    __half *gq, *gk, *gv, *go, *gx, *gw;
    cudaGetSymbolAddress((void**)&gq, g_Q);
    cudaGetSymbolAddress((void**)&gk, g_K);
    cudaGetSymbolAddress((void**)&gv, g_V);
    cudaGetSymbolAddress((void**)&go, g_O);
    cudaGetSymbolAddress((void**)&gx, g_Xh);
    cudaGetSymbolAddress((void**)&gw, g_Wh);

    static int attr_set = 0;
    if (!attr_set) {
        cudaFuncSetAttribute((const void*)proj_gemm<0>,
            cudaFuncAttributeMaxDynamicSharedMemorySize, PJ_SMEM_BYTES);
        cudaFuncSetAttribute((const void*)proj_gemm<1>,
            cudaFuncAttributeMaxDynamicSharedMemorySize, PJ_SMEM_BYTES);
        cudaFuncSetAttribute((const void*)fused_attn,
            cudaFuncAttributeMaxDynamicSharedMemorySize, FA_SMEM_BYTES);
        attr_set = 1;
    }

    dim3 blk(256);

    // fp32 -> fp16 pre-conversion (2 merged launches)
    const int NX8 = TOK * DMODEL / 8;
    const int NW8 = DMODEL * DMODEL / 8;
    const size_t XN = (size_t)TOK * DMODEL;
    const size_t WN = (size_t)DMODEL * DMODEL;
    cvt3<<<(3 * NX8) / 256, blk>>>(q, k, v, gx, NX8);
    cvt4<<<(4 * NW8) / 256, blk>>>(Wq, Wk, Wv, Wo, gw, NW8);

    // merged Q/K/V projections (z selects input/weight/output; z==2 -> V^T)
    dim3 gqkv(DMODEL / 128, TOK / 128, 3);
    proj_gemm<1><<<gqkv, blk, PJ_SMEM_BYTES>>>(gx, gx + XN, gx + 2 * XN,
                                               gw, gw + WN, gw + 2 * WN,
                                               bq, bk, bv, gq, gk, gv);

    // fused scores + softmax + attn-write + PV
    dim3 gfa(SEQ / QB, BATCH * HEADS);
    fused_attn<<<gfa, blk, FA_SMEM_BYTES>>>(gq, gk, gv, mask, attn, go);

    // output projection (fp16 A = g_O, fp32 out)
    dim3 gout(DMODEL / 128, TOK / 128, 1);
    proj_gemm<0><<<gout, blk, PJ_SMEM_BYTES>>>(go, go, go,
                                               gw + 3 * WN, gw + 3 * WN, gw + 3 * WN,
                                               bo, bo, bo, out, out, out);
}

// round 14
// speedup vs baseline: 1.0176x; 1.0176x over previous
#include <cuda_runtime.h>
#include <cuda_fp16.h>
#include <cstdint>

#define BATCH   4
#define HEADS   16
#define SEQ     2048
#define DMODEL  1024
#define HDIM    64
#define TOK     (BATCH*SEQ)       // 8192
// softmax in exp2 domain: scale = (1/sqrt(64)) * log2(e)
#define SCALE2  0.18033688011112042f

#define QB      128               // query rows per fused block
#define TC      64                // key tile

// -------- scratch (allocation-free rule: __device__ globals) --------
__device__ __half g_Q[BATCH*HEADS*SEQ*HDIM];   // [b][h][l][dh]
__device__ __half g_K[BATCH*HEADS*SEQ*HDIM];   // [b][h][t][dh]
__device__ __half g_V[BATCH*HEADS*SEQ*HDIM];   // [b][h][dh][t]  (transposed!)
__device__ __half g_O[TOK*DMODEL];             // [b*l][h*64+dv]
__device__ __half g_Xh[3*TOK*DMODEL];          // fp16 copies of q,k,v inputs
__device__ __half g_Wh[4*DMODEL*DMODEL];       // fp16 copies of Wq,Wk,Wv,Wo

__device__ __forceinline__ float ex2(float x) {
    float r;
    asm("ex2.approx.f32 %0, %1;" : "=f"(r) : "f"(x));
    return r;
}
__device__ __forceinline__ float lg2(float x) {
    float r;
    asm("lg2.approx.f32 %0, %1;" : "=f"(r) : "f"(x));
    return r;
}

__device__ __forceinline__ uint32_t f2h2(float lo, float hi) {
    __half2 h = __floats2half2_rn(lo, hi);
    return *reinterpret_cast<uint32_t*>(&h);
}

__device__ __forceinline__ void mma_f16(float c[4],
    uint32_t a0, uint32_t a1, uint32_t a2, uint32_t a3,
    uint32_t b0, uint32_t b1)
{
    asm volatile(
        "mma.sync.aligned.m16n8k16.row.col.f32.f16.f16.f32 "
        "{%0,%1,%2,%3}, {%4,%5,%6,%7}, {%8,%9}, {%0,%1,%2,%3};\n"
        : "+f"(c[0]), "+f"(c[1]), "+f"(c[2]), "+f"(c[3])
        : "r"(a0), "r"(a1), "r"(a2), "r"(a3), "r"(b0), "r"(b1));
}

__device__ __forceinline__ void ldsm_x4(uint32_t r[4], uint32_t addr) {
    asm volatile("ldmatrix.sync.aligned.m8n8.x4.shared.b16 {%0,%1,%2,%3}, [%4];"
        : "=r"(r[0]), "=r"(r[1]), "=r"(r[2]), "=r"(r[3]) : "r"(addr));
}
__device__ __forceinline__ void ldsm_x4_t(uint32_t r[4], uint32_t addr) {
    asm volatile("ldmatrix.sync.aligned.m8n8.x4.trans.shared.b16 {%0,%1,%2,%3}, [%4];"
        : "=r"(r[0]), "=r"(r[1]), "=r"(r[2]), "=r"(r[3]) : "r"(addr));
}

__device__ __forceinline__ uint32_t smem_u32(const void* p) {
    uint32_t a;
    asm("{ .reg .u64 t; cvta.to.shared.u64 t, %1; cvt.u32.u64 %0, t; }"
        : "=r"(a) : "l"(p));
    return a;
}
__device__ __forceinline__ void cp16(uint32_t dst, const void* src) {
    asm volatile("cp.async.cg.shared.global [%0], [%1], 16;" :: "r"(dst), "l"(src));
}
__device__ __forceinline__ void cp_commit() {
    asm volatile("cp.async.commit_group;" ::: "memory");
}
__device__ __forceinline__ void cp_wait1() {
    asm volatile("cp.async.wait_group 1;" ::: "memory");
}
__device__ __forceinline__ void cp_wait0() {
    asm volatile("cp.async.wait_group 0;" ::: "memory");
}

#define NEG_INF __int_as_float(0xff800000)

// ============================================================================
// fp32 -> fp16 converters, merged launches.
// ============================================================================
__device__ __forceinline__ void cvt_chunk(const float* __restrict__ src,
                                          __half* __restrict__ dst, int j)
{
    float4 a = ((const float4*)src)[j * 2];
    float4 b = ((const float4*)src)[j * 2 + 1];
    uint4 o;
    o.x = f2h2(a.x, a.y); o.y = f2h2(a.z, a.w);
    o.z = f2h2(b.x, b.y); o.w = f2h2(b.z, b.w);
    ((uint4*)dst)[j] = o;
}

__global__ void __launch_bounds__(256)
cvt3(const float* __restrict__ s0, const float* __restrict__ s1,
     const float* __restrict__ s2, __half* __restrict__ dst, int n8)
{
    int i = blockIdx.x * 256 + threadIdx.x;
    int which = i / n8, j = i - which * n8;
    const float* src = (which == 0) ? s0 : (which == 1) ? s1 : s2;
    cvt_chunk(src, dst + (size_t)which * n8 * 8, j);
}

__global__ void __launch_bounds__(256)
cvt4(const float* __restrict__ s0, const float* __restrict__ s1,
     const float* __restrict__ s2, const float* __restrict__ s3,
     __half* __restrict__ dst, int n8)
{
    int i = blockIdx.x * 256 + threadIdx.x;
    int which = i / n8, j = i - which * n8;
    const float* src = (which == 0) ? s0 : (which == 1) ? s1 :
                       (which == 2) ? s2 : s3;
    cvt_chunk(src, dst + (size_t)which * n8 * 8, j);
}

// ============================================================================
// fp16 projection GEMM: cp.async 3-stage, BK=64, ONE sync/iter (R13 version).
// C[8192x1024] = A(fp16) @ W(fp16) + bias(fp32).
//  EPI 0: fp32 row-major out.
//  EPI 1: fp16 scatter. z<2 -> [b][h][l][dh]; z==2 -> V transposed [b][h][dh][t].
// smem halves: As[3] 128x72 @ buf*9216 | Bs[3] 64x136 @ 27648+buf*8704
// total 53760 halves = 107520 B.
// ============================================================================
#define PAS 72
#define PBS 136
#define PJ_AS_H(buf) ((buf) * 9216)
#define PJ_BS_H(buf) (27648 + (buf) * 8704)
#define PJ_SMEM_BYTES 107520

template<int EPI>
__global__ void __launch_bounds__(256, 2)
proj_gemm(const __half* __restrict__ A0, const __half* __restrict__ A1,
          const __half* __restrict__ A2,
          const __half* __restrict__ W0, const __half* __restrict__ W1,
          const __half* __restrict__ W2,
          const float* __restrict__ b0, const float* __restrict__ b1,
          const float* __restrict__ b2,
          void* o0v, void* o1v, void* o2v)
{
    extern __shared__ char smc[];
    const uint32_t sb = smem_u32(smc);

    const int z = blockIdx.z;
    const __half* Ag  = (z == 0) ? A0 : (z == 1) ? A1 : A2;
    const __half* Wg  = (z == 0) ? W0 : (z == 1) ? W1 : W2;
    const float* bias = (z == 0) ? b0 : (z == 1) ? b1 : b2;
    void* outv        = (z == 0) ? o0v : (z == 1) ? o1v : o2v;

    const int tid  = threadIdx.x;
    const int warp = tid >> 5;
    const int lane = tid & 31;
    const int wm   = warp & 3;
    const int wn   = warp >> 2;
    const int g    = lane >> 2;
    const int t4   = lane & 3;
    const int l15  = lane & 15;
    const int lhi  = (lane >> 4) * 8;

    const int bn = blockIdx.x * 128;
    const int bm = blockIdx.y * 128;

    float acc[2][8][4];
    #pragma unroll
    for (int mi = 0; mi < 2; ++mi)
        #pragma unroll
        for (int ni = 0; ni < 8; ++ni)
            #pragma unroll
            for (int e = 0; e < 4; ++e) acc[mi][ni][e] = 0.f;

    auto issue = [&](int t, int buf) {
        const int kg = t * 64;
        const uint32_t ab = sb + PJ_AS_H(buf) * 2;
        #pragma unroll
        for (int i = 0; i < 4; ++i) {
            int idx = i * 256 + tid;
            int r = idx >> 3, c = idx & 7;
            cp16(ab + (r * PAS + c * 8) * 2, Ag + (size_t)(bm + r) * DMODEL + kg + c * 8);
        }
        const uint32_t bb = sb + PJ_BS_H(buf) * 2;
        #pragma unroll
        for (int i = 0; i < 4; ++i) {
            int idx = i * 256 + tid;
            int r = idx >> 4, c = idx & 15;
            cp16(bb + (r * PBS + c * 8) * 2, Wg + (size_t)(kg + r) * DMODEL + bn + c * 8);
        }
    };

    auto compute = [&](int buf, int kk) {
        const uint32_t asb = sb + PJ_AS_H(buf) * 2;
        const uint32_t bsb = sb + PJ_BS_H(buf) * 2;
        uint32_t af[2][4];
        #pragma unroll
        for (int mi = 0; mi < 2; ++mi)
            ldsm_x4(af[mi], asb + ((wm * 32 + mi * 16 + l15) * PAS + kk + lhi) * 2);
        uint32_t bf[4][4];
        #pragma unroll
        for (int p = 0; p < 4; ++p)
            ldsm_x4_t(bf[p], bsb + ((kk + l15) * PBS + wn * 64 + p * 16 + lhi) * 2);
        #pragma unroll
        for (int mi = 0; mi < 2; ++mi)
            #pragma unroll
            for (int p = 0; p < 4; ++p) {
                mma_f16(acc[mi][2 * p    ], af[mi][0], af[mi][1], af[mi][2], af[mi][3],
                        bf[p][0], bf[p][1]);
                mma_f16(acc[mi][2 * p + 1], af[mi][0], af[mi][1], af[mi][2], af[mi][3],
                        bf[p][2], bf[p][3]);
            }
    };

    issue(0, 0); cp_commit();
    issue(1, 1); cp_commit();
    for (int t = 0; t < 16; ++t) {
        cp_wait1();                            // tile t arrived
        __syncthreads();                       // visibility + buffer protection
        if (t + 2 < 16) issue(t + 2, (t + 2) % 3);
        cp_commit();                           // unconditional: 1 group/iter
        const int buf = t % 3;
        compute(buf, 0);
        compute(buf, 16);
        compute(buf, 32);
        compute(buf, 48);
    }

    // ---- epilogue ----
    #pragma unroll
    for (int mi = 0; mi < 2; ++mi) {
        #pragma unroll
        for (int ni = 0; ni < 8; ++ni) {
            int row0 = bm + wm * 32 + mi * 16 + g;
            int col  = bn + wn * 64 + ni * 8 + t4 * 2;
            float v00 = acc[mi][ni][0] + bias[col];
            float v01 = acc[mi][ni][1] + bias[col + 1];
            float v10 = acc[mi][ni][2] + bias[col];
            float v11 = acc[mi][ni][3] + bias[col + 1];
            if (EPI == 0) {
                float* out = (float*)outv;
                *(float2*)(out + (size_t)row0 * DMODEL + col) = make_float2(v00, v01);
                *(float2*)(out + (size_t)(row0 + 8) * DMODEL + col) = make_float2(v10, v11);
            } else {
                __half* out = (__half*)outv;
                int h  = col >> 6;
                int dh = col & 63;
                if (z < 2) {
                    #pragma unroll
                    for (int rr = 0; rr < 2; ++rr) {
                        int row = row0 + rr * 8;
                        int b = row >> 11, l = row & (SEQ - 1);
                        uint32_t pv = rr ? f2h2(v10, v11) : f2h2(v00, v01);
                        *(uint32_t*)(out + (((size_t)(b * HEADS + h)) * SEQ + l) * HDIM + dh) = pv;
                    }
                } else {
                    // V transposed: [b][h][dh][t]
                    #pragma unroll
                    for (int rr = 0; rr < 2; ++rr) {
                        int row = row0 + rr * 8;
                        int b = row >> 11, l = row & (SEQ - 1);
                        float va = rr ? v10 : v00;
                        float vb = rr ? v11 : v01;
                        size_t base = ((size_t)(b * HEADS + h)) * HDIM;
                        out[(base + dh    ) * SEQ + l] = __float2half_rn(va);
                        out[(base + dh + 1) * SEQ + l] = __float2half_rn(vb);
                    }
                }
            }
        }
    }
}

// ============================================================================
// Fused attention fp16 (R12 version, measured 455.7us): TC=64 both passes,
// 3-stage cp.async, ONE sync/iter; pass 2 folds 1/l into the exponent.
// smem halves: KS[3] @ buf*4608 | VS[3] @ 13824+buf*4608  ([64][72] each)
// Mf fp32 @ byte 55296 (2048 floats). Qs[128][72] overlays KS during init.
// ============================================================================
#define FST 72
#define KS_H(buf) ((buf) * 4608)
#define VS_H(buf) (13824 + (buf) * 4608)
#define FA_SMEM_BYTES 63488

__global__ void __launch_bounds__(256, 2)
fused_attn(const __half* __restrict__ gQ, const __half* __restrict__ gK,
           const __half* __restrict__ gVt, const int* __restrict__ mask,
           float* __restrict__ attnOut, __half* __restrict__ gO)
{
    extern __shared__ char smc[];
    __half* smh = (__half*)smc;
    float*  Mf  = (float*)(smc + 55296);
    const uint32_t sb = smem_u32(smc);

    const int tid  = threadIdx.x;
    const int lane = tid & 31;
    const int warp = tid >> 5;
    const int g    = lane >> 2;
    const int t4   = lane & 3;
    const int l15  = lane & 15;
    const int lhi  = (lane >> 4) * 8;
    const int wrow = warp * 16;

    const int qb = blockIdx.x * QB;
    const int bh = blockIdx.y;
    const int zb = bh >> 4;
    const int zh = bh & 15;

    const __half* Q  = gQ + ((size_t)bh * SEQ + qb) * HDIM;
    const __half* K  = gK + (size_t)bh * SEQ * HDIM;
    const __half* Vt = gVt + (size_t)bh * HDIM * SEQ;
    float* attn = attnOut + ((size_t)(zh * BATCH + zb) * SEQ + qb) * SEQ;

    // mask -> additive float
    #pragma unroll
    for (int i = 0; i < SEQ / 256; ++i) {
        int c = i * 256 + tid;
        Mf[c] = mask[zb * SEQ + c] ? NEG_INF : 0.f;
    }
    // Q tile -> smem (overlay on KS region)
    #pragma unroll
    for (int i = 0; i < 4; ++i) {
        int idx = i * 256 + tid;
        int r = idx >> 3, c = idx & 7;
        *(uint4*)(smh + r * FST + c * 8) = *(const uint4*)(Q + (size_t)r * HDIM + c * 8);
    }
    __syncthreads();

    // persistent Q A-fragments: 4 k16-steps x 4 regs
    uint32_t aq[4][4];
    #pragma unroll
    for (int ks = 0; ks < 4; ++ks)
        ldsm_x4(aq[ks], sb + ((wrow + l15) * FST + ks * 16 + lhi) * 2);
    __syncthreads();   // Qs dead before cp.async reuses region

    auto issueK = [&](int t, int buf) {
        const __half* Kt = K + (size_t)t * TC * HDIM;
        const uint32_t base = sb + KS_H(buf) * 2;
        #pragma unroll
        for (int i = 0; i < 2; ++i) {
            int idx = i * 256 + tid;
            int r = idx >> 3, c = idx & 7;
            cp16(base + (r * FST + c * 8) * 2, Kt + r * HDIM + c * 8);
        }
    };
    auto issueV = [&](int t, int buf) {
        const __half* Vs = Vt + (size_t)t * TC;   // [dv][t] tile
        const uint32_t base = sb + VS_H(buf) * 2;
        #pragma unroll
        for (int i = 0; i < 2; ++i) {
            int idx = i * 256 + tid;
            int r = idx >> 3, c = idx & 7;
            cp16(base + (r * FST + c * 8) * 2, Vs + (size_t)r * SEQ + c * 8);
        }
    };

    auto computeS = [&](float sacc[8][4], uint32_t ksb) {
        #pragma unroll
        for (int nt = 0; nt < 8; ++nt)
            #pragma unroll
            for (int e = 0; e < 4; ++e) sacc[nt][e] = 0.f;
        #pragma unroll
        for (int ks = 0; ks < 4; ++ks) {
            uint32_t bf[4][4];
            #pragma unroll
            for (int p = 0; p < 4; ++p)
                ldsm_x4(bf[p], ksb + ((p * 16 + l15) * FST + ks * 16 + lhi) * 2);
            #pragma unroll
            for (int p = 0; p < 4; ++p) {
                mma_f16(sacc[2 * p    ], aq[ks][0], aq[ks][1], aq[ks][2], aq[ks][3],
                        bf[p][0], bf[p][2]);
                mma_f16(sacc[2 * p + 1], aq[ks][0], aq[ks][1], aq[ks][2], aq[ks][3],
                        bf[p][1], bf[p][3]);
            }
        }
    };

    // ---------------- pass 1: online (m, l) ----------------
    float m0 = NEG_INF, m1 = NEG_INF, l0 = 0.f, l1 = 0.f;

    issueK(0, 0); cp_commit();
    issueK(1, 1); cp_commit();
    for (int t = 0; t < SEQ / TC; ++t) {
        cp_wait1();
        __syncthreads();
        if (t + 2 < SEQ / TC) issueK(t + 2, (t + 2) % 3);
        cp_commit();

        float sacc[8][4];
        computeS(sacc, sb + KS_H(t % 3) * 2);

        float tm0 = NEG_INF, tm1 = NEG_INF;
        #pragma unroll
        for (int nt = 0; nt < 8; ++nt) {
            float2 mk = *(const float2*)(Mf + t * TC + nt * 8 + t4 * 2);
            sacc[nt][0] = sacc[nt][0] * SCALE2 + mk.x;
            sacc[nt][1] = sacc[nt][1] * SCALE2 + mk.y;
            sacc[nt][2] = sacc[nt][2] * SCALE2 + mk.x;
            sacc[nt][3] = sacc[nt][3] * SCALE2 + mk.y;
            tm0 = fmaxf(tm0, fmaxf(sacc[nt][0], sacc[nt][1]));
            tm1 = fmaxf(tm1, fmaxf(sacc[nt][2], sacc[nt][3]));
        }
        tm0 = fmaxf(tm0, __shfl_xor_sync(0xffffffffu, tm0, 1));
        tm0 = fmaxf(tm0, __shfl_xor_sync(0xffffffffu, tm0, 2));
        tm1 = fmaxf(tm1, __shfl_xor_sync(0xffffffffu, tm1, 1));
        tm1 = fmaxf(tm1, __shfl_xor_sync(0xffffffffu, tm1, 2));

        float mn0 = fmaxf(m0, tm0), mn1 = fmaxf(m1, tm1);
        float ms0 = (mn0 == NEG_INF) ? 0.f : mn0;
        float ms1 = (mn1 == NEG_INF) ? 0.f : mn1;

        float sum0 = 0.f, sum1 = 0.f;
        #pragma unroll
        for (int nt = 0; nt < 8; ++nt) {
            sum0 += ex2(sacc[nt][0] - ms0) + ex2(sacc[nt][1] - ms0);
            sum1 += ex2(sacc[nt][2] - ms1) + ex2(sacc[nt][3] - ms1);
        }
        sum0 += __shfl_xor_sync(0xffffffffu, sum0, 1);
        sum0 += __shfl_xor_sync(0xffffffffu, sum0, 2);
        sum1 += __shfl_xor_sync(0xffffffffu, sum1, 1);
        sum1 += __shfl_xor_sync(0xffffffffu, sum1, 2);

        float a0 = (m0 == NEG_INF) ? 0.f : ex2(m0 - ms0);
        float a1 = (m1 == NEG_INF) ? 0.f : ex2(m1 - ms1);
        l0 = l0 * a0 + sum0;
        l1 = l1 * a1 + sum1;
        m0 = mn0; m1 = mn1;
    }

    // fold 1/l into exponent: c = m + log2(l)  (masked rows -> c = 0, s=-inf -> p=0)
    const float c0 = (l0 > 0.f) ? ((m0 == NEG_INF) ? 0.f : m0) + lg2(l0) : 0.f;
    const float c1 = (l1 > 0.f) ? ((m1 == NEG_INF) ? 0.f : m1) + lg2(l1) : 0.f;

    // ---------------- pass 2: recompute + P write + PV ----------------
    float oacc[8][4];
    #pragma unroll
    for (int nt = 0; nt < 8; ++nt)
        #pragma unroll
        for (int e = 0; e < 4; ++e) oacc[nt][e] = 0.f;

    cp_wait0();        // drain pass-1 prefetch groups
    __syncthreads();   // pass-1 compute fully done before re-staging buffers
    issueK(0, 0); issueV(0, 0); cp_commit();
    issueK(1, 1); issueV(1, 1); cp_commit();
    for (int t = 0; t < SEQ / TC; ++t) {
        cp_wait1();
        __syncthreads();
        if (t + 2 < SEQ / TC) { issueK(t + 2, (t + 2) % 3); issueV(t + 2, (t + 2) % 3); }
        cp_commit();

        float sacc[8][4];
        computeS(sacc, sb + KS_H(t % 3) * 2);
        const uint32_t vsb = sb + VS_H(t % 3) * 2;

        // normalize in place + streaming attn write (float2, sector-aligned)
        #pragma unroll
        for (int nt = 0; nt < 8; ++nt) {
            float2 mk = *(const float2*)(Mf + t * TC + nt * 8 + t4 * 2);
            sacc[nt][0] = ex2(sacc[nt][0] * SCALE2 + (mk.x - c0));
            sacc[nt][1] = ex2(sacc[nt][1] * SCALE2 + (mk.y - c0));
            sacc[nt][2] = ex2(sacc[nt][2] * SCALE2 + (mk.x - c1));
            sacc[nt][3] = ex2(sacc[nt][3] * SCALE2 + (mk.y - c1));
            float2* d0 = (float2*)(attn + (size_t)(wrow + g) * SEQ + t * TC + nt * 8 + t4 * 2);
            __stcs(d0, make_float2(sacc[nt][0], sacc[nt][1]));
            __stcs((float2*)((float*)d0 + 8 * SEQ), make_float2(sacc[nt][2], sacc[nt][3]));
        }

        // PV: A-frags straight from sacc (fp16 C-layout == A-layout)
        #pragma unroll
        for (int j = 0; j < 4; ++j) {
            uint32_t pa0 = f2h2(sacc[2 * j][0],     sacc[2 * j][1]);
            uint32_t pa1 = f2h2(sacc[2 * j][2],     sacc[2 * j][3]);
            uint32_t pa2 = f2h2(sacc[2 * j + 1][0], sacc[2 * j + 1][1]);
            uint32_t pa3 = f2h2(sacc[2 * j + 1][2], sacc[2 * j + 1][3]);
            uint32_t bf[4][4];
            #pragma unroll
            for (int p = 0; p < 4; ++p)
                ldsm_x4(bf[p], vsb + ((p * 16 + l15) * FST + j * 16 + lhi) * 2);
            #pragma unroll
            for (int p = 0; p < 4; ++p) {
                mma_f16(oacc[2 * p    ], pa0, pa1, pa2, pa3, bf[p][0], bf[p][2]);
                mma_f16(oacc[2 * p + 1], pa0, pa1, pa2, pa3, bf[p][1], bf[p][3]);
            }
        }
    }

    // write O block (fp16) to g_O [b*l][h*64+dv]
    #pragma unroll
    for (int nt = 0; nt < 8; ++nt) {
        int col = nt * 8 + t4 * 2;
        size_t r0 = ((size_t)zb * SEQ + qb + wrow + g) * DMODEL + zh * HDIM + col;
        *(uint32_t*)(gO + r0)               = f2h2(oacc[nt][0], oacc[nt][1]);
        *(uint32_t*)(gO + r0 + 8 * DMODEL)  = f2h2(oacc[nt][2], oacc[nt][3]);
    }
}

// ============================================================================
extern "C" void kernel_launch(void* const* d_in, const int* in_sizes, int n_in,
                              void* d_out, int out_size)
{
    const float* q    = (const float*)d_in[0];
    const float* k    = (const float*)d_in[1];
    const float* v    = (const float*)d_in[2];
    const int*   mask = (const int*)d_in[3];
    const float* Wq = (const float*)d_in[4];
    const float* bq = (const float*)d_in[5];
    const float* Wk = (const float*)d_in[6];
    const float* bk = (const float*)d_in[7];
    const float* Wv = (const float*)d_in[8];
    const float* bv = (const float*)d_in[9];
    const float* Wo = (const float*)d_in[10];
    const float* bo = (const float*)d_in[11];

    float* out  = (float*)d_out;                         // [4,2048,1024]
    float* attn = out + (size_t)TOK * DMODEL;            // [16,4,2048,2048]

    __half *gq, *gk, *gv, *go, *gx, *gw;
    cudaGetSymbolAddress((void**)&gq, g_Q);
    cudaGetSymbolAddress((void**)&gk, g_K);
    cudaGetSymbolAddress((void**)&gv, g_V);
    cudaGetSymbolAddress((void**)&go, g_O);
    cudaGetSymbolAddress((void**)&gx, g_Xh);
    cudaGetSymbolAddress((void**)&gw, g_Wh);

    static int attr_set = 0;
    if (!attr_set) {
        cudaFuncSetAttribute((const void*)proj_gemm<0>,
            cudaFuncAttributeMaxDynamicSharedMemorySize, PJ_SMEM_BYTES);
        cudaFuncSetAttribute((const void*)proj_gemm<1>,
            cudaFuncAttributeMaxDynamicSharedMemorySize, PJ_SMEM_BYTES);
        cudaFuncSetAttribute((const void*)fused_attn,
            cudaFuncAttributeMaxDynamicSharedMemorySize, FA_SMEM_BYTES);
        attr_set = 1;
    }

    dim3 blk(256);

    // fp32 -> fp16 pre-conversion (2 merged launches)
    const int NX8 = TOK * DMODEL / 8;
    const int NW8 = DMODEL * DMODEL / 8;
    const size_t XN = (size_t)TOK * DMODEL;
    const size_t WN = (size_t)DMODEL * DMODEL;
    cvt3<<<(3 * NX8) / 256, blk>>>(q, k, v, gx, NX8);
    cvt4<<<(4 * NW8) / 256, blk>>>(Wq, Wk, Wv, Wo, gw, NW8);

    // merged Q/K/V projections (z selects input/weight/output; z==2 -> V^T)
    dim3 gqkv(DMODEL / 128, TOK / 128, 3);
    proj_gemm<1><<<gqkv, blk, PJ_SMEM_BYTES>>>(gx, gx + XN, gx + 2 * XN,
                                               gw, gw + WN, gw + 2 * WN,
                                               bq, bk, bv, gq, gk, gv);

    // fused scores + softmax + attn-write + PV
    dim3 gfa(SEQ / QB, BATCH * HEADS);
    fused_attn<<<gfa, blk, FA_SMEM_BYTES>>>(gq, gk, gv, mask, attn, go);

    // output projection (fp16 A = g_O, fp32 out)
    dim3 gout(DMODEL / 128, TOK / 128, 1);
    proj_gemm<0><<<gout, blk, PJ_SMEM_BYTES>>>(go, go, go,
                                               gw + 3 * WN, gw + 3 * WN, gw + 3 * WN,
                                               bo, bo, bo, out, out, out);
}

// round 15
// speedup vs baseline: 1.0590x; 1.0407x over previous
#include <cuda_runtime.h>
#include <cuda_fp16.h>
#include <cstdint>

#define BATCH   4
#define HEADS   16
#define SEQ     2048
#define DMODEL  1024
#define HDIM    64
#define TOK     (BATCH*SEQ)       // 8192
// softmax in exp2 domain: scale = (1/sqrt(64)) * log2(e)
#define SCALE2  0.18033688011112042f

#define QB      128               // query rows per fused block
#define TC      64                // key tile

// -------- scratch (allocation-free rule: __device__ globals) --------
__device__ __half g_Q[BATCH*HEADS*SEQ*HDIM];   // [b][h][l][dh]
__device__ __half g_K[BATCH*HEADS*SEQ*HDIM];   // [b][h][t][dh]
__device__ __half g_V[BATCH*HEADS*SEQ*HDIM];   // [b][h][dh][t]  (transposed!)
__device__ __half g_O[TOK*DMODEL];             // [b*l][h*64+dv]
__device__ __half g_Xh[3*TOK*DMODEL];          // fp16 copies of q,k,v inputs
__device__ __half g_Wh[4*DMODEL*DMODEL];       // fp16 copies of Wq,Wk,Wv,Wo

__device__ __forceinline__ float ex2(float x) {
    float r;
    asm("ex2.approx.f32 %0, %1;" : "=f"(r) : "f"(x));
    return r;
}
__device__ __forceinline__ float lg2(float x) {
    float r;
    asm("lg2.approx.f32 %0, %1;" : "=f"(r) : "f"(x));
    return r;
}

__device__ __forceinline__ uint32_t f2h2(float lo, float hi) {
    __half2 h = __floats2half2_rn(lo, hi);
    return *reinterpret_cast<uint32_t*>(&h);
}

__device__ __forceinline__ void mma_f16(float c[4],
    uint32_t a0, uint32_t a1, uint32_t a2, uint32_t a3,
    uint32_t b0, uint32_t b1)
{
    asm volatile(
        "mma.sync.aligned.m16n8k16.row.col.f32.f16.f16.f32 "
        "{%0,%1,%2,%3}, {%4,%5,%6,%7}, {%8,%9}, {%0,%1,%2,%3};\n"
        : "+f"(c[0]), "+f"(c[1]), "+f"(c[2]), "+f"(c[3])
        : "r"(a0), "r"(a1), "r"(a2), "r"(a3), "r"(b0), "r"(b1));
}

__device__ __forceinline__ void ldsm_x4(uint32_t r[4], uint32_t addr) {
    asm volatile("ldmatrix.sync.aligned.m8n8.x4.shared.b16 {%0,%1,%2,%3}, [%4];"
        : "=r"(r[0]), "=r"(r[1]), "=r"(r[2]), "=r"(r[3]) : "r"(addr));
}
__device__ __forceinline__ void ldsm_x4_t(uint32_t r[4], uint32_t addr) {
    asm volatile("ldmatrix.sync.aligned.m8n8.x4.trans.shared.b16 {%0,%1,%2,%3}, [%4];"
        : "=r"(r[0]), "=r"(r[1]), "=r"(r[2]), "=r"(r[3]) : "r"(addr));
}

__device__ __forceinline__ uint32_t smem_u32(const void* p) {
    uint32_t a;
    asm("{ .reg .u64 t; cvta.to.shared.u64 t, %1; cvt.u32.u64 %0, t; }"
        : "=r"(a) : "l"(p));
    return a;
}
__device__ __forceinline__ void cp16(uint32_t dst, const void* src) {
    asm volatile("cp.async.cg.shared.global [%0], [%1], 16;" :: "r"(dst), "l"(src));
}
__device__ __forceinline__ void cp_commit() {
    asm volatile("cp.async.commit_group;" ::: "memory");
}
__device__ __forceinline__ void cp_wait1() {
    asm volatile("cp.async.wait_group 1;" ::: "memory");
}
__device__ __forceinline__ void cp_wait0() {
    asm volatile("cp.async.wait_group 0;" ::: "memory");
}

#define NEG_INF __int_as_float(0xff800000)

// ============================================================================
// fp32 -> fp16 converters, merged launches.
// ============================================================================
__device__ __forceinline__ void cvt_chunk(const float* __restrict__ src,
                                          __half* __restrict__ dst, int j)
{
    float4 a = ((const float4*)src)[j * 2];
    float4 b = ((const float4*)src)[j * 2 + 1];
    uint4 o;
    o.x = f2h2(a.x, a.y); o.y = f2h2(a.z, a.w);
    o.z = f2h2(b.x, b.y); o.w = f2h2(b.z, b.w);
    ((uint4*)dst)[j] = o;
}

__global__ void __launch_bounds__(256)
cvt3(const float* __restrict__ s0, const float* __restrict__ s1,
     const float* __restrict__ s2, __half* __restrict__ dst, int n8)
{
    int i = blockIdx.x * 256 + threadIdx.x;
    int which = i / n8, j = i - which * n8;
    const float* src = (which == 0) ? s0 : (which == 1) ? s1 : s2;
    cvt_chunk(src, dst + (size_t)which * n8 * 8, j);
}

__global__ void __launch_bounds__(256)
cvt4(const float* __restrict__ s0, const float* __restrict__ s1,
     const float* __restrict__ s2, const float* __restrict__ s3,
     __half* __restrict__ dst, int n8)
{
    int i = blockIdx.x * 256 + threadIdx.x;
    int which = i / n8, j = i - which * n8;
    const float* src = (which == 0) ? s0 : (which == 1) ? s1 :
                       (which == 2) ? s2 : s3;
    cvt_chunk(src, dst + (size_t)which * n8 * 8, j);
}

// ============================================================================
// fp16 projection GEMM: cp.async 3-stage, BK=64, ONE sync/iter.
// C[8192x1024] = A(fp16) @ W(fp16) + bias(fp32).
//  EPI 0: fp32 row-major out.
//  EPI 1: fp16 scatter. z<2 -> [b][h][l][dh]; z==2 -> V transposed [b][h][dh][t].
// smem halves: As[3] 128x72 @ buf*9216 | Bs[3] 64x136 @ 27648+buf*8704
// ============================================================================
#define PAS 72
#define PBS 136
#define PJ_AS_H(buf) ((buf) * 9216)
#define PJ_BS_H(buf) (27648 + (buf) * 8704)
#define PJ_SMEM_BYTES 107520

template<int EPI>
__global__ void __launch_bounds__(256, 2)
proj_gemm(const __half* __restrict__ A0, const __half* __restrict__ A1,
          const __half* __restrict__ A2,
          const __half* __restrict__ W0, const __half* __restrict__ W1,
          const __half* __restrict__ W2,
          const float* __restrict__ b0, const float* __restrict__ b1,
          const float* __restrict__ b2,
          void* o0v, void* o1v, void* o2v)
{
    extern __shared__ char smc[];
    const uint32_t sb = smem_u32(smc);

    const int z = blockIdx.z;
    const __half* Ag  = (z == 0) ? A0 : (z == 1) ? A1 : A2;
    const __half* Wg  = (z == 0) ? W0 : (z == 1) ? W1 : W2;
    const float* bias = (z == 0) ? b0 : (z == 1) ? b1 : b2;
    void* outv        = (z == 0) ? o0v : (z == 1) ? o1v : o2v;

    const int tid  = threadIdx.x;
    const int warp = tid >> 5;
    const int lane = tid & 31;
    const int wm   = warp & 3;
    const int wn   = warp >> 2;
    const int g    = lane >> 2;
    const int t4   = lane & 3;
    const int l15  = lane & 15;
    const int lhi  = (lane >> 4) * 8;

    const int bn = blockIdx.x * 128;
    const int bm = blockIdx.y * 128;

    float acc[2][8][4];
    #pragma unroll
    for (int mi = 0; mi < 2; ++mi)
        #pragma unroll
        for (int ni = 0; ni < 8; ++ni)
            #pragma unroll
            for (int e = 0; e < 4; ++e) acc[mi][ni][e] = 0.f;

    auto issue = [&](int t, int buf) {
        const int kg = t * 64;
        const uint32_t ab = sb + PJ_AS_H(buf) * 2;
        #pragma unroll
        for (int i = 0; i < 4; ++i) {
            int idx = i * 256 + tid;
            int r = idx >> 3, c = idx & 7;
            cp16(ab + (r * PAS + c * 8) * 2, Ag + (size_t)(bm + r) * DMODEL + kg + c * 8);
        }
        const uint32_t bb = sb + PJ_BS_H(buf) * 2;
        #pragma unroll
        for (int i = 0; i < 4; ++i) {
            int idx = i * 256 + tid;
            int r = idx >> 4, c = idx & 15;
            cp16(bb + (r * PBS + c * 8) * 2, Wg + (size_t)(kg + r) * DMODEL + bn + c * 8);
        }
    };

    auto compute = [&](int buf, int kk) {
        const uint32_t asb = sb + PJ_AS_H(buf) * 2;
        const uint32_t bsb = sb + PJ_BS_H(buf) * 2;
        uint32_t af[2][4];
        #pragma unroll
        for (int mi = 0; mi < 2; ++mi)
            ldsm_x4(af[mi], asb + ((wm * 32 + mi * 16 + l15) * PAS + kk + lhi) * 2);
        uint32_t bf[4][4];
        #pragma unroll
        for (int p = 0; p < 4; ++p)
            ldsm_x4_t(bf[p], bsb + ((kk + l15) * PBS + wn * 64 + p * 16 + lhi) * 2);
        #pragma unroll
        for (int mi = 0; mi < 2; ++mi)
            #pragma unroll
            for (int p = 0; p < 4; ++p) {
                mma_f16(acc[mi][2 * p    ], af[mi][0], af[mi][1], af[mi][2], af[mi][3],
                        bf[p][0], bf[p][1]);
                mma_f16(acc[mi][2 * p + 1], af[mi][0], af[mi][1], af[mi][2], af[mi][3],
                        bf[p][2], bf[p][3]);
            }
    };

    issue(0, 0); cp_commit();
    issue(1, 1); cp_commit();
    for (int t = 0; t < 16; ++t) {
        cp_wait1();                            // tile t arrived
        __syncthreads();                       // visibility + buffer protection
        if (t + 2 < 16) issue(t + 2, (t + 2) % 3);
        cp_commit();                           // unconditional: 1 group/iter
        const int buf = t % 3;
        compute(buf, 0);
        compute(buf, 16);
        compute(buf, 32);
        compute(buf, 48);
    }

    // ---- epilogue ----
    #pragma unroll
    for (int mi = 0; mi < 2; ++mi) {
        #pragma unroll
        for (int ni = 0; ni < 8; ++ni) {
            int row0 = bm + wm * 32 + mi * 16 + g;
            int col  = bn + wn * 64 + ni * 8 + t4 * 2;
            float v00 = acc[mi][ni][0] + bias[col];
            float v01 = acc[mi][ni][1] + bias[col + 1];
            float v10 = acc[mi][ni][2] + bias[col];
            float v11 = acc[mi][ni][3] + bias[col + 1];
            if (EPI == 0) {
                float* out = (float*)outv;
                *(float2*)(out + (size_t)row0 * DMODEL + col) = make_float2(v00, v01);
                *(float2*)(out + (size_t)(row0 + 8) * DMODEL + col) = make_float2(v10, v11);
            } else {
                __half* out = (__half*)outv;
                int h  = col >> 6;
                int dh = col & 63;
                if (z < 2) {
                    #pragma unroll
                    for (int rr = 0; rr < 2; ++rr) {
                        int row = row0 + rr * 8;
                        int b = row >> 11, l = row & (SEQ - 1);
                        uint32_t pv = rr ? f2h2(v10, v11) : f2h2(v00, v01);
                        *(uint32_t*)(out + (((size_t)(b * HEADS + h)) * SEQ + l) * HDIM + dh) = pv;
                    }
                } else {
                    // V transposed: [b][h][dh][t]
                    #pragma unroll
                    for (int rr = 0; rr < 2; ++rr) {
                        int row = row0 + rr * 8;
                        int b = row >> 11, l = row & (SEQ - 1);
                        float va = rr ? v10 : v00;
                        float vb = rr ? v11 : v01;
                        size_t base = ((size_t)(b * HEADS + h)) * HDIM;
                        out[(base + dh    ) * SEQ + l] = __float2half_rn(va);
                        out[(base + dh + 1) * SEQ + l] = __float2half_rn(vb);
                    }
                }
            }
        }
    }
}

// ============================================================================
// Fused attention fp16: TC=64 both passes, 3-stage cp.async, ONE sync/iter.
// Pass 1: FIXED-SHIFT softmax denominator (no max tracking — logits are
// range-safe in fp32 exp2 domain): per-thread l += ex2(s*SCALE2+mk); lane
// reduction once after the loop. Pass 2 folds c=log2(l) into the exponent.
// smem halves: KS[3] @ buf*4608 | VS[3] @ 13824+buf*4608  ([64][72] each)
// Mf fp32 @ byte 55296 (2048 floats). Qs[128][72] overlays KS during init.
// ============================================================================
#define FST 72
#define KS_H(buf) ((buf) * 4608)
#define VS_H(buf) (13824 + (buf) * 4608)
#define FA_SMEM_BYTES 63488

__global__ void __launch_bounds__(256, 2)
fused_attn(const __half* __restrict__ gQ, const __half* __restrict__ gK,
           const __half* __restrict__ gVt, const int* __restrict__ mask,
           float* __restrict__ attnOut, __half* __restrict__ gO)
{
    extern __shared__ char smc[];
    __half* smh = (__half*)smc;
    float*  Mf  = (float*)(smc + 55296);
    const uint32_t sb = smem_u32(smc);

    const int tid  = threadIdx.x;
    const int lane = tid & 31;
    const int warp = tid >> 5;
    const int g    = lane >> 2;
    const int t4   = lane & 3;
    const int l15  = lane & 15;
    const int lhi  = (lane >> 4) * 8;
    const int wrow = warp * 16;

    const int qb = blockIdx.x * QB;
    const int bh = blockIdx.y;
    const int zb = bh >> 4;
    const int zh = bh & 15;

    const __half* Q  = gQ + ((size_t)bh * SEQ + qb) * HDIM;
    const __half* K  = gK + (size_t)bh * SEQ * HDIM;
    const __half* Vt = gVt + (size_t)bh * HDIM * SEQ;
    float* attn = attnOut + ((size_t)(zh * BATCH + zb) * SEQ + qb) * SEQ;

    // mask -> additive float
    #pragma unroll
    for (int i = 0; i < SEQ / 256; ++i) {
        int c = i * 256 + tid;
        Mf[c] = mask[zb * SEQ + c] ? NEG_INF : 0.f;
    }
    // Q tile -> smem (overlay on KS region)
    #pragma unroll
    for (int i = 0; i < 4; ++i) {
        int idx = i * 256 + tid;
        int r = idx >> 3, c = idx & 7;
        *(uint4*)(smh + r * FST + c * 8) = *(const uint4*)(Q + (size_t)r * HDIM + c * 8);
    }
    __syncthreads();

    // persistent Q A-fragments: 4 k16-steps x 4 regs
    uint32_t aq[4][4];
    #pragma unroll
    for (int ks = 0; ks < 4; ++ks)
        ldsm_x4(aq[ks], sb + ((wrow + l15) * FST + ks * 16 + lhi) * 2);
    __syncthreads();   // Qs dead before cp.async reuses region

    auto issueK = [&](int t, int buf) {
        const __half* Kt = K + (size_t)t * TC * HDIM;
        const uint32_t base = sb + KS_H(buf) * 2;
        #pragma unroll
        for (int i = 0; i < 2; ++i) {
            int idx = i * 256 + tid;
            int r = idx >> 3, c = idx & 7;
            cp16(base + (r * FST + c * 8) * 2, Kt + r * HDIM + c * 8);
        }
    };
    auto issueV = [&](int t, int buf) {
        const __half* Vs = Vt + (size_t)t * TC;   // [dv][t] tile
        const uint32_t base = sb + VS_H(buf) * 2;
        #pragma unroll
        for (int i = 0; i < 2; ++i) {
            int idx = i * 256 + tid;
            int r = idx >> 3, c = idx & 7;
            cp16(base + (r * FST + c * 8) * 2, Vs + (size_t)r * SEQ + c * 8);
        }
    };

    auto computeS = [&](float sacc[8][4], uint32_t ksb) {
        #pragma unroll
        for (int nt = 0; nt < 8; ++nt)
            #pragma unroll
            for (int e = 0; e < 4; ++e) sacc[nt][e] = 0.f;
        #pragma unroll
        for (int ks = 0; ks < 4; ++ks) {
            uint32_t bf[4][4];
            #pragma unroll
            for (int p = 0; p < 4; ++p)
                ldsm_x4(bf[p], ksb + ((p * 16 + l15) * FST + ks * 16 + lhi) * 2);
            #pragma unroll
            for (int p = 0; p < 4; ++p) {
                mma_f16(sacc[2 * p    ], aq[ks][0], aq[ks][1], aq[ks][2], aq[ks][3],
                        bf[p][0], bf[p][2]);
                mma_f16(sacc[2 * p + 1], aq[ks][0], aq[ks][1], aq[ks][2], aq[ks][3],
                        bf[p][1], bf[p][3]);
            }
        }
    };

    // ------- pass 1: fixed-shift denominator l (no max tracking) -------
    float l0 = 0.f, l1 = 0.f;

    issueK(0, 0); cp_commit();
    issueK(1, 1); cp_commit();
    for (int t = 0; t < SEQ / TC; ++t) {
        cp_wait1();
        __syncthreads();
        if (t + 2 < SEQ / TC) issueK(t + 2, (t + 2) % 3);
        cp_commit();

        float sacc[8][4];
        computeS(sacc, sb + KS_H(t % 3) * 2);

        #pragma unroll
        for (int nt = 0; nt < 8; ++nt) {
            float2 mk = *(const float2*)(Mf + t * TC + nt * 8 + t4 * 2);
            l0 += ex2(sacc[nt][0] * SCALE2 + mk.x) + ex2(sacc[nt][1] * SCALE2 + mk.y);
            l1 += ex2(sacc[nt][2] * SCALE2 + mk.x) + ex2(sacc[nt][3] * SCALE2 + mk.y);
        }
    }
    // single cross-lane reduction (4 lanes per row group)
    l0 += __shfl_xor_sync(0xffffffffu, l0, 1);
    l0 += __shfl_xor_sync(0xffffffffu, l0, 2);
    l1 += __shfl_xor_sync(0xffffffffu, l1, 1);
    l1 += __shfl_xor_sync(0xffffffffu, l1, 2);

    // normalization constant in exp2 domain (fully-masked row: l=0 -> c=0,
    // pass-2 args stay -inf -> p = 0, matching nan_to_num behavior)
    const float c0 = (l0 > 0.f) ? lg2(l0) : 0.f;
    const float c1 = (l1 > 0.f) ? lg2(l1) : 0.f;

    // ---------------- pass 2: recompute + P write + PV ----------------
    float oacc[8][4];
    #pragma unroll
    for (int nt = 0; nt < 8; ++nt)
        #pragma unroll
        for (int e = 0; e < 4; ++e) oacc[nt][e] = 0.f;

    cp_wait0();        // drain pass-1 prefetch groups
    __syncthreads();   // pass-1 compute fully done before re-staging buffers
    issueK(0, 0); issueV(0, 0); cp_commit();
    issueK(1, 1); issueV(1, 1); cp_commit();
    for (int t = 0; t < SEQ / TC; ++t) {
        cp_wait1();
        __syncthreads();
        if (t + 2 < SEQ / TC) { issueK(t + 2, (t + 2) % 3); issueV(t + 2, (t + 2) % 3); }
        cp_commit();

        float sacc[8][4];
        computeS(sacc, sb + KS_H(t % 3) * 2);
        const uint32_t vsb = sb + VS_H(t % 3) * 2;

        // normalize in place + streaming attn write (float2, sector-aligned)
        #pragma unroll
        for (int nt = 0; nt < 8; ++nt) {
            float2 mk = *(const float2*)(Mf + t * TC + nt * 8 + t4 * 2);
            sacc[nt][0] = ex2(sacc[nt][0] * SCALE2 + (mk.x - c0));
            sacc[nt][1] = ex2(sacc[nt][1] * SCALE2 + (mk.y - c0));
            sacc[nt][2] = ex2(sacc[nt][2] * SCALE2 + (mk.x - c1));
            sacc[nt][3] = ex2(sacc[nt][3] * SCALE2 + (mk.y - c1));
            float2* d0 = (float2*)(attn + (size_t)(wrow + g) * SEQ + t * TC + nt * 8 + t4 * 2);
            __stcs(d0, make_float2(sacc[nt][0], sacc[nt][1]));
            __stcs((float2*)((float*)d0 + 8 * SEQ), make_float2(sacc[nt][2], sacc[nt][3]));
        }

        // PV: A-frags straight from sacc (fp16 C-layout == A-layout)
        #pragma unroll
        for (int j = 0; j < 4; ++j) {
            uint32_t pa0 = f2h2(sacc[2 * j][0],     sacc[2 * j][1]);
            uint32_t pa1 = f2h2(sacc[2 * j][2],     sacc[2 * j][3]);
            uint32_t pa2 = f2h2(sacc[2 * j + 1][0], sacc[2 * j + 1][1]);
            uint32_t pa3 = f2h2(sacc[2 * j + 1][2], sacc[2 * j + 1][3]);
            uint32_t bf[4][4];
            #pragma unroll
            for (int p = 0; p < 4; ++p)
                ldsm_x4(bf[p], vsb + ((p * 16 + l15) * FST + j * 16 + lhi) * 2);
            #pragma unroll
            for (int p = 0; p < 4; ++p) {
                mma_f16(oacc[2 * p    ], pa0, pa1, pa2, pa3, bf[p][0], bf[p][2]);
                mma_f16(oacc[2 * p + 1], pa0, pa1, pa2, pa3, bf[p][1], bf[p][3]);
            }
        }
    }

    // write O block (fp16) to g_O [b*l][h*64+dv]
    #pragma unroll
    for (int nt = 0; nt < 8; ++nt) {
        int col = nt * 8 + t4 * 2;
        size_t r0 = ((size_t)zb * SEQ + qb + wrow + g) * DMODEL + zh * HDIM + col;
        *(uint32_t*)(gO + r0)               = f2h2(oacc[nt][0], oacc[nt][1]);
        *(uint32_t*)(gO + r0 + 8 * DMODEL)  = f2h2(oacc[nt][2], oacc[nt][3]);
    }
}

// ============================================================================
extern "C" void kernel_launch(void* const* d_in, const int* in_sizes, int n_in,
                              void* d_out, int out_size)
{
    const float* q    = (const float*)d_in[0];
    const float* k    = (const float*)d_in[1];
    const float* v    = (const float*)d_in[2];
    const int*   mask = (const int*)d_in[3];
    const float* Wq = (const float*)d_in[4];
    const float* bq = (const float*)d_in[5];
    const float* Wk = (const float*)d_in[6];
    const float* bk = (const float*)d_in[7];
    const float* Wv = (const float*)d_in[8];
    const float* bv = (const float*)d_in[9];
    const float* Wo = (const float*)d_in[10];
    const float* bo = (const float*)d_in[11];

    float* out  = (float*)d_out;                         // [4,2048,1024]
    float* attn = out + (size_t)TOK * DMODEL;            // [16,4,2048,2048]

    __half *gq, *gk, *gv, *go, *gx, *gw;
    cudaGetSymbolAddress((void**)&gq, g_Q);
    cudaGetSymbolAddress((void**)&gk, g_K);
    cudaGetSymbolAddress((void**)&gv, g_V);
    cudaGetSymbolAddress((void**)&go, g_O);
    cudaGetSymbolAddress((void**)&gx, g_Xh);
    cudaGetSymbolAddress((void**)&gw, g_Wh);

    static int attr_set = 0;
    if (!attr_set) {
        cudaFuncSetAttribute((const void*)proj_gemm<0>,
            cudaFuncAttributeMaxDynamicSharedMemorySize, PJ_SMEM_BYTES);
        cudaFuncSetAttribute((const void*)proj_gemm<1>,
            cudaFuncAttributeMaxDynamicSharedMemorySize, PJ_SMEM_BYTES);
        cudaFuncSetAttribute((const void*)fused_attn,
            cudaFuncAttributeMaxDynamicSharedMemorySize, FA_SMEM_BYTES);
        attr_set = 1;
    }

    dim3 blk(256);

    // fp32 -> fp16 pre-conversion (2 merged launches)
    const int NX8 = TOK * DMODEL / 8;
    const int NW8 = DMODEL * DMODEL / 8;
    const size_t XN = (size_t)TOK * DMODEL;
    const size_t WN = (size_t)DMODEL * DMODEL;
    cvt3<<<(3 * NX8) / 256, blk>>>(q, k, v, gx, NX8);
    cvt4<<<(4 * NW8) / 256, blk>>>(Wq, Wk, Wv, Wo, gw, NW8);

    // merged Q/K/V projections (z selects input/weight/output; z==2 -> V^T)
    dim3 gqkv(DMODEL / 128, TOK / 128, 3);
    proj_gemm<1><<<gqkv, blk, PJ_SMEM_BYTES>>>(gx, gx + XN, gx + 2 * XN,
                                               gw, gw + WN, gw + 2 * WN,
                                               bq, bk, bv, gq, gk, gv);

    // fused scores + softmax + attn-write + PV
    dim3 gfa(SEQ / QB, BATCH * HEADS);
    fused_attn<<<gfa, blk, FA_SMEM_BYTES>>>(gq, gk, gv, mask, attn, go);

    // output projection (fp16 A = g_O, fp32 out)
    dim3 gout(DMODEL / 128, TOK / 128, 1);
    proj_gemm<0><<<gout, blk, PJ_SMEM_BYTES>>>(go, go, go,
                                               gw + 3 * WN, gw + 3 * WN, gw + 3 * WN,
                                               bo, bo, bo, out, out, out);
}